// round 2
// baseline (speedup 1.0000x reference)
#include <cuda_runtime.h>
#include <cstdint>
#include <math.h>

#define LAYERS 3
#define UNITS  1024
#define BATCH  128
#define TSEQ   256
#define NC     (3*UNITS)      // 3072
#define MXW    (BATCH*TSEQ)   // 32768

// ---------------- scratch (static device memory; no allocations) ----------------
__device__ __align__(128) float g_xw[(size_t)MXW * NC];          // 402 MB: x@W + b0 per layer
__device__ __align__(128) float g_x [(size_t)MXW * UNITS];       // 134 MB: current layer input (tf32-rounded)
__device__ __align__(128) float g_Wc[(size_t)LAYERS * UNITS * NC]; // tf32-rounded W
__device__ __align__(128) float g_Uc[(size_t)LAYERS * UNITS * NC]; // tf32-rounded U
__device__ __align__(128) float g_h [2][BATCH * UNITS];          // h double buffer (fp32)

// ---------------- helpers ----------------
__device__ __forceinline__ float tf32r(float v) {
    unsigned r;
    asm("cvt.rna.tf32.f32 %0, %1;" : "=r"(r) : "f"(v));
    return __uint_as_float(r);
}

__device__ __forceinline__ void mma_tf32(float* c, const unsigned* a, const unsigned* b) {
    asm volatile(
        "mma.sync.aligned.m16n8k8.row.col.f32.tf32.tf32.f32 "
        "{%0,%1,%2,%3}, {%4,%5,%6,%7}, {%8,%9}, {%0,%1,%2,%3};"
        : "+f"(c[0]), "+f"(c[1]), "+f"(c[2]), "+f"(c[3])
        : "r"(a[0]), "r"(a[1]), "r"(a[2]), "r"(a[3]), "r"(b[0]), "r"(b[1]));
}

// ---------------- conversion / init / finalize kernels ----------------
__global__ void cvt_weights_kernel(const float* __restrict__ W, const float* __restrict__ U) {
    size_t n = (size_t)LAYERS * UNITS * NC;
    for (size_t i = blockIdx.x * (size_t)blockDim.x + threadIdx.x; i < n;
         i += (size_t)gridDim.x * blockDim.x) {
        g_Wc[i] = tf32r(W[i]);
        g_Uc[i] = tf32r(U[i]);
    }
}

__global__ void cvt_input_kernel(const float* __restrict__ X) {
    size_t n = (size_t)MXW * UNITS;
    for (size_t i = blockIdx.x * (size_t)blockDim.x + threadIdx.x; i < n;
         i += (size_t)gridDim.x * blockDim.x) {
        g_x[i] = tf32r(X[i]);
    }
}

__global__ void init_h_kernel(const float* __restrict__ h0, int layer) {
    int i = blockIdx.x * blockDim.x + threadIdx.x;  // i = b*UNITS + u
    if (i < BATCH * UNITS) g_h[0][i] = h0[(size_t)i * LAYERS + layer];
}

__global__ void copy_state_kernel(float* __restrict__ outs, int layer) {
    int i = blockIdx.x * blockDim.x + threadIdx.x;  // i = b*UNITS + u  -> outs[b][u][layer]
    if (i < BATCH * UNITS) outs[(size_t)i * LAYERS + layer] = g_h[0][i];
}

// ---------------- XW GEMM: g_xw = g_x @ Wc[l] + b0[l] ----------------
#define BM 128
#define BN 128
#define BK 32
#define ASTR (BM + 1)  // padded smem strides (bank-conflict relief)
#define BSTR (BN + 1)

__global__ __launch_bounds__(256) void gemm_xw_kernel(int layer, const float* __restrict__ bias) {
    __shared__ float As[BK * ASTR];   // [k][m]
    __shared__ float Bs[BK * BSTR];   // [k][n]

    const float* A  = g_x;
    const float* Bw = g_Wc + (size_t)layer * UNITS * NC;
    float*       C  = g_xw;

    int tid = threadIdx.x;
    int lane = tid & 31, wid = tid >> 5;
    int gid = lane >> 2, tig = lane & 3;
    int wm = wid & 3, wn = wid >> 2;           // 4 x 2 warps
    int mb = wm * 32, nb = wn * 64;            // warp tile 32 x 64
    int bm0 = blockIdx.y * BM, bn0 = blockIdx.x * BN;

    float acc[2][8][4];
#pragma unroll
    for (int i = 0; i < 2; i++)
#pragma unroll
        for (int j = 0; j < 8; j++)
#pragma unroll
            for (int q = 0; q < 4; q++) acc[i][j][q] = 0.f;

    for (int k0 = 0; k0 < UNITS; k0 += BK) {
        // A tile: 128 rows x 32 k (pre-rounded tf32), store transposed [k][m]
#pragma unroll
        for (int j = 0; j < 4; j++) {
            int i = tid + j * 256;           // 0..1023 float4s
            int r = i >> 3, c4 = i & 7;
            const float4 v = *(const float4*)(A + (size_t)(bm0 + r) * UNITS + k0 + c4 * 4);
            As[(c4 * 4 + 0) * ASTR + r] = v.x;
            As[(c4 * 4 + 1) * ASTR + r] = v.y;
            As[(c4 * 4 + 2) * ASTR + r] = v.z;
            As[(c4 * 4 + 3) * ASTR + r] = v.w;
        }
        // B tile: 32 k x 128 n (pre-rounded tf32)
#pragma unroll
        for (int j = 0; j < 4; j++) {
            int i = tid + j * 256;
            int r = i >> 5, c4 = i & 31;
            const float4 v = *(const float4*)(Bw + (size_t)(k0 + r) * NC + bn0 + c4 * 4);
            Bs[r * BSTR + c4 * 4 + 0] = v.x;
            Bs[r * BSTR + c4 * 4 + 1] = v.y;
            Bs[r * BSTR + c4 * 4 + 2] = v.z;
            Bs[r * BSTR + c4 * 4 + 3] = v.w;
        }
        __syncthreads();
#pragma unroll
        for (int kk = 0; kk < BK; kk += 8) {
            unsigned a[2][4], bf[8][2];
#pragma unroll
            for (int mt = 0; mt < 2; mt++) {
                int m = mb + mt * 16 + gid;
                a[mt][0] = __float_as_uint(As[(kk + tig) * ASTR + m]);
                a[mt][1] = __float_as_uint(As[(kk + tig) * ASTR + m + 8]);
                a[mt][2] = __float_as_uint(As[(kk + tig + 4) * ASTR + m]);
                a[mt][3] = __float_as_uint(As[(kk + tig + 4) * ASTR + m + 8]);
            }
#pragma unroll
            for (int nt = 0; nt < 8; nt++) {
                int n = nb + nt * 8 + gid;
                bf[nt][0] = __float_as_uint(Bs[(kk + tig) * BSTR + n]);
                bf[nt][1] = __float_as_uint(Bs[(kk + tig + 4) * BSTR + n]);
            }
#pragma unroll
            for (int mt = 0; mt < 2; mt++)
#pragma unroll
                for (int nt = 0; nt < 8; nt++) mma_tf32(acc[mt][nt], a[mt], bf[nt]);
        }
        __syncthreads();
    }
    // epilogue: + bias, store
#pragma unroll
    for (int mt = 0; mt < 2; mt++) {
#pragma unroll
        for (int nt = 0; nt < 8; nt++) {
            int m = bm0 + mb + mt * 16 + gid;
            int n = bn0 + nb + nt * 8 + 2 * tig;
            float bv0 = bias[n], bv1 = bias[n + 1];
            C[(size_t)m * NC + n]           = acc[mt][nt][0] + bv0;
            C[(size_t)m * NC + n + 1]       = acc[mt][nt][1] + bv1;
            C[(size_t)(m + 8) * NC + n]     = acc[mt][nt][2] + bv0;
            C[(size_t)(m + 8) * NC + n + 1] = acc[mt][nt][3] + bv1;
        }
    }
}

// ---------------- fused GRU step: hu = h@U + b1, gates, h/y writes ----------------
#define SBM 64     // batch rows per CTA
#define SNU 16     // u-indices per CTA -> 48 output cols (z|r|hh)
#define SNC 48
#define SBK 32
#define SASTR (SBM + 1)  // 65
#define SBSTR (SNC + 1)  // 49

__global__ __launch_bounds__(128) void gru_step_kernel(int layer, const float* __restrict__ bias1,
                                                       float* __restrict__ ylast, int t, int hb,
                                                       int wfp) {
    __shared__ float sm[SBK * SASTR + SBK * SBSTR];  // 3648 floats; reused as HU [64][49]
    float* As = sm;
    float* Bs = sm + SBK * SASTR;

    const float* Uc    = g_Uc + (size_t)layer * UNITS * NC;
    const float* hprev = g_h[hb];
    float*       hnext = g_h[1 - hb];

    int tid = threadIdx.x, lane = tid & 31, wid = tid >> 5;
    int gid = lane >> 2, tig = lane & 3;
    int wm = wid & 1, wn = wid >> 1;  // 2 x 2 warps, warp tile 32 x 24
    int mb = wm * 32, nb = wn * 24;
    int u0  = blockIdx.x * SNU;
    int bm0 = blockIdx.y * SBM;

    float acc[2][3][4] = {};

    for (int k0 = 0; k0 < UNITS; k0 += SBK) {
        // A tile: h 64 x 32 (fp32 -> tf32 round here), transposed [k][m]
#pragma unroll
        for (int j = 0; j < 4; j++) {
            int i = tid + j * 128;          // 0..511 float4s
            int r = i >> 3, c4 = i & 7;
            const float4 v = *(const float4*)(hprev + (size_t)(bm0 + r) * UNITS + k0 + c4 * 4);
            As[(c4 * 4 + 0) * SASTR + r] = tf32r(v.x);
            As[(c4 * 4 + 1) * SASTR + r] = tf32r(v.y);
            As[(c4 * 4 + 2) * SASTR + r] = tf32r(v.z);
            As[(c4 * 4 + 3) * SASTR + r] = tf32r(v.w);
        }
        // B tile: U slice 32 k x 48 cols (cols = [u0..u0+16) of each gate)
#pragma unroll
        for (int j = 0; j < 3; j++) {
            int i = tid + j * 128;          // 0..383 float4s
            int r = i / 12, c4 = i % 12;
            int c = c4 * 4;                 // 0..44
            int gate = c >> 4, uu = c & 15;
            const float4 v =
                *(const float4*)(Uc + (size_t)(k0 + r) * NC + gate * UNITS + u0 + uu);
            Bs[r * SBSTR + c + 0] = v.x;
            Bs[r * SBSTR + c + 1] = v.y;
            Bs[r * SBSTR + c + 2] = v.z;
            Bs[r * SBSTR + c + 3] = v.w;
        }
        __syncthreads();
#pragma unroll
        for (int kk = 0; kk < SBK; kk += 8) {
            unsigned a[2][4], bf[3][2];
#pragma unroll
            for (int mt = 0; mt < 2; mt++) {
                int m = mb + mt * 16 + gid;
                a[mt][0] = __float_as_uint(As[(kk + tig) * SASTR + m]);
                a[mt][1] = __float_as_uint(As[(kk + tig) * SASTR + m + 8]);
                a[mt][2] = __float_as_uint(As[(kk + tig + 4) * SASTR + m]);
                a[mt][3] = __float_as_uint(As[(kk + tig + 4) * SASTR + m + 8]);
            }
#pragma unroll
            for (int nt = 0; nt < 3; nt++) {
                int n = nb + nt * 8 + gid;
                bf[nt][0] = __float_as_uint(Bs[(kk + tig) * SBSTR + n]);
                bf[nt][1] = __float_as_uint(Bs[(kk + tig + 4) * SBSTR + n]);
            }
#pragma unroll
            for (int mt = 0; mt < 2; mt++)
#pragma unroll
                for (int nt = 0; nt < 3; nt++) mma_tf32(acc[mt][nt], a[mt], bf[nt]);
        }
        __syncthreads();
    }

    // stage hu accumulators to smem so each (m, u) sees all 3 gates
    float* HU = sm;  // [64][49]
#pragma unroll
    for (int mt = 0; mt < 2; mt++) {
#pragma unroll
        for (int nt = 0; nt < 3; nt++) {
            int m = mb + mt * 16 + gid;
            int n = nb + nt * 8 + 2 * tig;
            HU[m * SBSTR + n]           = acc[mt][nt][0];
            HU[m * SBSTR + n + 1]       = acc[mt][nt][1];
            HU[(m + 8) * SBSTR + n]     = acc[mt][nt][2];
            HU[(m + 8) * SBSTR + n + 1] = acc[mt][nt][3];
        }
    }
    __syncthreads();

    // gate epilogue: 64 x 16 elements, 8 per thread
#pragma unroll
    for (int j = 0; j < 8; j++) {
        int i  = tid + j * 128;
        int m  = i >> 4, uu = i & 15;
        int bb = bm0 + m, u = u0 + uu;
        size_t xrow = ((size_t)bb * TSEQ + t) * NC;
        float xz = g_xw[xrow + u];
        float xr = g_xw[xrow + UNITS + u];
        float xh = g_xw[xrow + 2 * UNITS + u];
        float hz = HU[m * SBSTR + uu]      + bias1[u];
        float hr = HU[m * SBSTR + 16 + uu] + bias1[UNITS + u];
        float hh = HU[m * SBSTR + 32 + uu] + bias1[2 * UNITS + u];
        float hp = hprev[(size_t)bb * UNITS + u];

        float z    = 1.f / (1.f + expf(-(xz + hz)));
        float r    = 1.f / (1.f + expf(-(xr + hr)));
        float hhat = tanhf(xh + r * hh);
        float hn   = z * hp + (1.f - z) * hhat;

        hnext[(size_t)bb * UNITS + u] = hn;
        size_t yi = ((size_t)bb * TSEQ + t) * UNITS + u;
        if (wfp) ylast[yi] = hn;                 // final layer: fp32 to d_out
        else     g_x[yi] = tf32r(hn);            // feed next layer pre-rounded
    }
}

// ---------------- host launcher ----------------
extern "C" void kernel_launch(void* const* d_in, const int* in_sizes, int n_in,
                              void* d_out, int out_size) {
    (void)in_sizes; (void)n_in; (void)out_size;
    const float* x_in = (const float*)d_in[0];
    const float* h0   = (const float*)d_in[1];
    const float* W    = (const float*)d_in[2];
    const float* U    = (const float*)d_in[3];
    const float* b    = (const float*)d_in[4];
    float* out        = (float*)d_out;
    float* out_states = out + (size_t)MXW * UNITS;

    cvt_weights_kernel<<<4096, 256>>>(W, U);
    cvt_input_kernel<<<8192, 256>>>(x_in);

    for (int l = 0; l < LAYERS; l++) {
        init_h_kernel<<<(BATCH * UNITS + 255) / 256, 256>>>(h0, l);
        gemm_xw_kernel<<<dim3(NC / BN, MXW / BM), 256>>>(l, b + (size_t)l * 2 * NC);
        int wfp = (l == LAYERS - 1);
        for (int t = 0; t < TSEQ; t++) {
            gru_step_kernel<<<dim3(UNITS / SNU, BATCH / SBM), 128>>>(
                l, b + (size_t)l * 2 * NC + NC, out, t, t & 1, wfp);
        }
        copy_state_kernel<<<(BATCH * UNITS + 255) / 256, 256>>>(out_states, l);
    }
}

// round 3
// speedup vs baseline: 1.8869x; 1.8869x over previous
#include <cuda_runtime.h>
#include <cstdint>
#include <math.h>

#define LAYERS 3
#define UNITS  1024
#define BATCH  128
#define TSEQ   256
#define NC     (3*UNITS)      // 3072
#define MXW    (BATCH*TSEQ)   // 32768

// persistent-kernel geometry
#define NCTA   128
#define UB     8              // u-indices per CTA
#define CCOLS  24             // 3 gates x UB
#define KC     64             // k-chunk staged per cp.async round
#define NCHUNK (UNITS/KC)     // 16
#define PASTR  136            // smem A row stride (floats): 16B-aligned, conflict-free

// ---------------- scratch (static device memory) ----------------
__device__ __align__(128) float g_xw[(size_t)MXW * NC];            // [t][b][3U] layout
__device__ __align__(128) float g_x [(size_t)MXW * UNITS];         // layer input, tf32-rounded
__device__ __align__(128) float g_Wc[(size_t)LAYERS * UNITS * NC];
__device__ __align__(128) float g_Uc[(size_t)LAYERS * UNITS * NC];
__device__ __align__(128) float g_hT[2][UNITS][BATCH];             // transposed, tf32-rounded h
__device__ unsigned g_bar_cnt = 0;
__device__ volatile unsigned g_bar_gen = 0;

// ---------------- helpers ----------------
__device__ __forceinline__ float tf32r(float v) {
    unsigned r;
    asm("cvt.rna.tf32.f32 %0, %1;" : "=r"(r) : "f"(v));
    return __uint_as_float(r);
}

__device__ __forceinline__ void mma_tf32(float* c, const unsigned* a, const unsigned* b) {
    asm volatile(
        "mma.sync.aligned.m16n8k8.row.col.f32.tf32.tf32.f32 "
        "{%0,%1,%2,%3}, {%4,%5,%6,%7}, {%8,%9}, {%0,%1,%2,%3};"
        : "+f"(c[0]), "+f"(c[1]), "+f"(c[2]), "+f"(c[3])
        : "r"(a[0]), "r"(a[1]), "r"(a[2]), "r"(a[3]), "r"(b[0]), "r"(b[1]));
}

__device__ __forceinline__ void cp16(float* dst, const float* src) {
    unsigned ds = (unsigned)__cvta_generic_to_shared(dst);
    asm volatile("cp.async.cg.shared.global [%0], [%1], 16;" :: "r"(ds), "l"(src));
}
__device__ __forceinline__ void cp_commit() { asm volatile("cp.async.commit_group;"); }
template <int N> __device__ __forceinline__ void cp_wait() {
    asm volatile("cp.async.wait_group %0;" :: "n"(N));
}

// grid-wide barrier: all NCTA CTAs co-resident (1 CTA/SM, grid <= 148)
__device__ __forceinline__ void grid_sync() {
    __threadfence();
    __syncthreads();
    if (threadIdx.x == 0) {
        unsigned gen = g_bar_gen;
        if (atomicAdd(&g_bar_cnt, 1u) == NCTA - 1) {
            g_bar_cnt = 0;
            __threadfence();
            g_bar_gen = gen + 1;
        } else {
            while (g_bar_gen == gen) { __nanosleep(32); }
        }
        __threadfence();
    }
    __syncthreads();
}

// ---------------- conversion kernels ----------------
__global__ void cvt_weights_kernel(const float* __restrict__ W, const float* __restrict__ U) {
    size_t n = (size_t)LAYERS * UNITS * NC;
    for (size_t i = blockIdx.x * (size_t)blockDim.x + threadIdx.x; i < n;
         i += (size_t)gridDim.x * blockDim.x) {
        g_Wc[i] = tf32r(W[i]);
        g_Uc[i] = tf32r(U[i]);
    }
}

__global__ void cvt_input_kernel(const float* __restrict__ X) {
    size_t n = (size_t)MXW * UNITS;
    for (size_t i = blockIdx.x * (size_t)blockDim.x + threadIdx.x; i < n;
         i += (size_t)gridDim.x * blockDim.x) {
        g_x[i] = tf32r(X[i]);
    }
}

// ---------------- XW GEMM: g_xw[t][b][:] = (g_x @ Wc[l]) + b0[l] ----------------
#define BM 128
#define BN 128
#define BK 32
#define ASTR (BM + 1)
#define BSTR (BN + 1)

__global__ __launch_bounds__(256) void gemm_xw_kernel(int layer, const float* __restrict__ bias) {
    __shared__ float As[BK * ASTR];   // [k][m]
    __shared__ float Bs[BK * BSTR];   // [k][n]

    const float* A  = g_x;
    const float* Bw = g_Wc + (size_t)layer * UNITS * NC;
    float*       C  = g_xw;

    int tid = threadIdx.x;
    int lane = tid & 31, wid = tid >> 5;
    int gid = lane >> 2, tig = lane & 3;
    int wm = wid & 3, wn = wid >> 2;
    int mb = wm * 32, nb = wn * 64;
    int bm0 = blockIdx.y * BM, bn0 = blockIdx.x * BN;

    float acc[2][8][4];
#pragma unroll
    for (int i = 0; i < 2; i++)
#pragma unroll
        for (int j = 0; j < 8; j++)
#pragma unroll
            for (int q = 0; q < 4; q++) acc[i][j][q] = 0.f;

    for (int k0 = 0; k0 < UNITS; k0 += BK) {
#pragma unroll
        for (int j = 0; j < 4; j++) {
            int i = tid + j * 256;
            int r = i >> 3, c4 = i & 7;
            const float4 v = *(const float4*)(A + (size_t)(bm0 + r) * UNITS + k0 + c4 * 4);
            As[(c4 * 4 + 0) * ASTR + r] = v.x;
            As[(c4 * 4 + 1) * ASTR + r] = v.y;
            As[(c4 * 4 + 2) * ASTR + r] = v.z;
            As[(c4 * 4 + 3) * ASTR + r] = v.w;
        }
#pragma unroll
        for (int j = 0; j < 4; j++) {
            int i = tid + j * 256;
            int r = i >> 5, c4 = i & 31;
            const float4 v = *(const float4*)(Bw + (size_t)(k0 + r) * NC + bn0 + c4 * 4);
            Bs[r * BSTR + c4 * 4 + 0] = v.x;
            Bs[r * BSTR + c4 * 4 + 1] = v.y;
            Bs[r * BSTR + c4 * 4 + 2] = v.z;
            Bs[r * BSTR + c4 * 4 + 3] = v.w;
        }
        __syncthreads();
#pragma unroll
        for (int kk = 0; kk < BK; kk += 8) {
            unsigned a[2][4], bf[8][2];
#pragma unroll
            for (int mt = 0; mt < 2; mt++) {
                int m = mb + mt * 16 + gid;
                a[mt][0] = __float_as_uint(As[(kk + tig) * ASTR + m]);
                a[mt][1] = __float_as_uint(As[(kk + tig) * ASTR + m + 8]);
                a[mt][2] = __float_as_uint(As[(kk + tig + 4) * ASTR + m]);
                a[mt][3] = __float_as_uint(As[(kk + tig + 4) * ASTR + m + 8]);
            }
#pragma unroll
            for (int nt = 0; nt < 8; nt++) {
                int n = nb + nt * 8 + gid;
                bf[nt][0] = __float_as_uint(Bs[(kk + tig) * BSTR + n]);
                bf[nt][1] = __float_as_uint(Bs[(kk + tig + 4) * BSTR + n]);
            }
#pragma unroll
            for (int mt = 0; mt < 2; mt++)
#pragma unroll
                for (int nt = 0; nt < 8; nt++) mma_tf32(acc[mt][nt], a[mt], bf[nt]);
        }
        __syncthreads();
    }
    // epilogue: + bias, store into [t][b][:] layout
#pragma unroll
    for (int mt = 0; mt < 2; mt++) {
#pragma unroll
        for (int nt = 0; nt < 8; nt++) {
            int m0 = bm0 + mb + mt * 16 + gid;       // global row = b*TSEQ + t
            int n  = bn0 + nb + nt * 8 + 2 * tig;
            float bv0 = bias[n], bv1 = bias[n + 1];
            int t0 = m0 & (TSEQ - 1), b0r = m0 >> 8;
            int m1 = m0 + 8;
            int t1 = m1 & (TSEQ - 1), b1r = m1 >> 8;
            size_t r0 = ((size_t)t0 * BATCH + b0r) * NC + n;
            size_t r1 = ((size_t)t1 * BATCH + b1r) * NC + n;
            C[r0]     = acc[mt][nt][0] + bv0;
            C[r0 + 1] = acc[mt][nt][1] + bv1;
            C[r1]     = acc[mt][nt][2] + bv0;
            C[r1 + 1] = acc[mt][nt][3] + bv1;
        }
    }
}

// ---------------- persistent GRU layer kernel: all 256 timesteps ----------------
// 128 CTAs x 128 threads. CTA owns u0..u0+7 (24 cols: z|r|hh). U slice in SMEM.
// h state in registers; tf32 copy published transposed for cp.async A-loads.
__global__ __launch_bounds__(128, 1)
void gru_layer_kernel(int layer, const float* __restrict__ h0,
                      const float* __restrict__ bias1,
                      float* __restrict__ yout, float* __restrict__ out_states,
                      int is_last) {
    extern __shared__ float sm[];
    float* Us    = sm;                              // [1024][24]
    float* Ab    = sm + UNITS * CCOLS;              // 2 x [KC][PASTR]
    float* sbias = Ab + 2 * KC * PASTR;             // [24]

    const int tid  = threadIdx.x;
    const int lane = tid & 31, wid = tid >> 5;
    const int gid  = lane >> 2, tig = lane & 3;
    const int mb   = wid * 32;                      // warp tile: 32 rows x 24 cols
    const int u0   = blockIdx.x * UB;

    // load U slice (once per layer)
    const float* Uc = g_Uc + (size_t)layer * UNITS * NC;
    for (int i = tid; i < UNITS * 6; i += 128) {
        int k = i / 6, c4 = i % 6;
        int gate = c4 >> 1, uu = (c4 & 1) * 4;
        float4 v = *(const float4*)(Uc + (size_t)k * NC + gate * UNITS + u0 + uu);
        float* d = Us + k * CCOLS + c4 * 4;
        d[0] = v.x; d[1] = v.y; d[2] = v.z; d[3] = v.w;
    }
    if (tid < CCOLS) {
        int gate = tid >> 3, uu = tid & 7;
        sbias[tid] = bias1[gate * UNITS + u0 + uu];
    }

    // init h: full precision in regs, tf32 copy to g_hT[0]
    float hreg[4][2];
#pragma unroll
    for (int r = 0; r < 4; r++) {
        int bb = mb + (r >> 1) * 16 + (r & 1) * 8 + gid;
#pragma unroll
        for (int ui = 0; ui < 2; ui++) {
            int u = u0 + 2 * tig + ui;
            float hv = h0[((size_t)bb * UNITS + u) * LAYERS + layer];
            hreg[r][ui] = hv;
            g_hT[0][u][bb] = tf32r(hv);
        }
    }
    grid_sync();

    for (int t = 0; t < TSEQ; t++) {
        const int rb = t & 1;
        const float* hT = &g_hT[rb][0][0];
        float acc[2][3][4];
#pragma unroll
        for (int i = 0; i < 2; i++)
#pragma unroll
            for (int j = 0; j < 3; j++)
#pragma unroll
                for (int q = 0; q < 4; q++) acc[i][j][q] = 0.f;

        // prologue: chunk 0 -> buf 0
#pragma unroll
        for (int w = 0; w < 16; w++) {
            int i = tid + w * 128;
            int k = i >> 5, c16 = i & 31;
            cp16(Ab + k * PASTR + c16 * 4, hT + k * BATCH + c16 * 4);
        }
        cp_commit();

        for (int c = 0; c < NCHUNK; c++) {
            if (c + 1 < NCHUNK) {
                float* db = Ab + ((c + 1) & 1) * KC * PASTR;
                const float* sb = hT + (size_t)(c + 1) * KC * BATCH;
#pragma unroll
                for (int w = 0; w < 16; w++) {
                    int i = tid + w * 128;
                    int k = i >> 5, c16 = i & 31;
                    cp16(db + k * PASTR + c16 * 4, sb + k * BATCH + c16 * 4);
                }
                cp_commit();
                cp_wait<1>();
            } else {
                cp_wait<0>();
            }
            __syncthreads();

            const float* A = Ab + (c & 1) * KC * PASTR;
            const int kbase = c * KC;
#pragma unroll
            for (int kk = 0; kk < KC; kk += 8) {
                unsigned a[2][4], bf[3][2];
#pragma unroll
                for (int mt = 0; mt < 2; mt++) {
                    int m = mb + mt * 16 + gid;
                    a[mt][0] = __float_as_uint(A[(kk + tig) * PASTR + m]);
                    a[mt][1] = __float_as_uint(A[(kk + tig) * PASTR + m + 8]);
                    a[mt][2] = __float_as_uint(A[(kk + tig + 4) * PASTR + m]);
                    a[mt][3] = __float_as_uint(A[(kk + tig + 4) * PASTR + m + 8]);
                }
#pragma unroll
                for (int nt = 0; nt < 3; nt++) {
                    int n = nt * 8 + gid;
                    bf[nt][0] = __float_as_uint(Us[(kbase + kk + tig) * CCOLS + n]);
                    bf[nt][1] = __float_as_uint(Us[(kbase + kk + tig + 4) * CCOLS + n]);
                }
#pragma unroll
                for (int mt = 0; mt < 2; mt++)
#pragma unroll
                    for (int nt = 0; nt < 3; nt++) mma_tf32(acc[mt][nt], a[mt], bf[nt]);
            }
            __syncthreads();
        }

        // epilogue: gates in registers (nt == gate), h blend in fp32
        const int wb = 1 - rb;
#pragma unroll
        for (int r = 0; r < 4; r++) {
            int mt = r >> 1, q = r & 1;
            int bb = mb + mt * 16 + q * 8 + gid;
            const float* xwrow = g_xw + ((size_t)t * BATCH + bb) * NC + u0 + 2 * tig;
            float2 xz = *(const float2*)(xwrow);
            float2 xr = *(const float2*)(xwrow + UNITS);
            float2 xh = *(const float2*)(xwrow + 2 * UNITS);
            float hn2[2];
#pragma unroll
            for (int ui = 0; ui < 2; ui++) {
                int uu = 2 * tig + ui;
                float hz = acc[mt][0][q * 2 + ui] + sbias[uu];
                float hr = acc[mt][1][q * 2 + ui] + sbias[8 + uu];
                float hh = acc[mt][2][q * 2 + ui] + sbias[16 + uu];
                float xzv = ui ? xz.y : xz.x;
                float xrv = ui ? xr.y : xr.x;
                float xhv = ui ? xh.y : xh.x;
                float z    = 1.f / (1.f + __expf(-(xzv + hz)));
                float rg   = 1.f / (1.f + __expf(-(xrv + hr)));
                float hhat = tanhf(xhv + rg * hh);
                float hn   = z * hreg[r][ui] + (1.f - z) * hhat;
                hreg[r][ui] = hn;
                g_hT[wb][u0 + uu][bb] = tf32r(hn);
                hn2[ui] = hn;
            }
            size_t yi = ((size_t)bb * TSEQ + t) * UNITS + u0 + 2 * tig;
            if (is_last) {
                *(float2*)(yout + yi) = make_float2(hn2[0], hn2[1]);
            } else {
                *(float2*)(g_x + yi) = make_float2(tf32r(hn2[0]), tf32r(hn2[1]));
            }
        }
        grid_sync();
    }

    // final states (from full-precision registers)
#pragma unroll
    for (int r = 0; r < 4; r++) {
        int bb = mb + (r >> 1) * 16 + (r & 1) * 8 + gid;
#pragma unroll
        for (int ui = 0; ui < 2; ui++) {
            int u = u0 + 2 * tig + ui;
            out_states[((size_t)bb * UNITS + u) * LAYERS + layer] = hreg[r][ui];
        }
    }
}

// ---------------- host launcher ----------------
#define PERS_SMEM ((UNITS * CCOLS + 2 * KC * PASTR + 32) * 4)

extern "C" void kernel_launch(void* const* d_in, const int* in_sizes, int n_in,
                              void* d_out, int out_size) {
    (void)in_sizes; (void)n_in; (void)out_size;
    const float* x_in = (const float*)d_in[0];
    const float* h0   = (const float*)d_in[1];
    const float* W    = (const float*)d_in[2];
    const float* U    = (const float*)d_in[3];
    const float* b    = (const float*)d_in[4];
    float* out        = (float*)d_out;
    float* out_states = out + (size_t)MXW * UNITS;

    cudaFuncSetAttribute(gru_layer_kernel,
                         cudaFuncAttributeMaxDynamicSharedMemorySize, PERS_SMEM);

    cvt_weights_kernel<<<4096, 256>>>(W, U);
    cvt_input_kernel<<<8192, 256>>>(x_in);

    for (int l = 0; l < LAYERS; l++) {
        gemm_xw_kernel<<<dim3(NC / BN, MXW / BM), 256>>>(l, b + (size_t)l * 2 * NC);
        gru_layer_kernel<<<NCTA, 128, PERS_SMEM>>>(
            l, h0, b + (size_t)l * 2 * NC + NC, out, out_states, l == LAYERS - 1);
    }
}